// round 2
// baseline (speedup 1.0000x reference)
#include <cuda_runtime.h>
#include <math.h>

// Problem constants
#define NPROTO  10
#define NCLS    10
#define NPATCH  196
#define BIMG    8192
#define NFEAT   (NPROTO * NPATCH)   // 1960

// Decomposition
#define NCHUNK  16                  // patch-split across warps
#define RIMG    4                   // images per lane
#define NGROUP  (BIMG / (32 * RIMG))// 64 image groups (128 images / warp)

// scratch: [chunk][group][class][r][lane]
__device__ float g_scratch[NCHUNK * NGROUP * NCLS * RIMG * 32]; // 5.24 MB

// ---------------------------------------------------------------------------
// Stage 1: fused patch-kernel + partial GEMM.
// ---------------------------------------------------------------------------
__global__ void __launch_bounds__(128)
quanv_stage1(const float* __restrict__ x,
             const float* __restrict__ proto,
             const float* __restrict__ W)
{
    extern __shared__ float sm[];
    float* sW  = sm;              // 19600 floats
    float* sPc = sm + 19600;      // 40 floats: cos(proto/2)
    float* sPs = sm + 19640;      // 40 floats: sin(proto/2)

    const int tid = threadIdx.x;

    for (int i = tid; i < NCLS * NFEAT; i += 128) sW[i] = W[i];
    if (tid < NPROTO * 4) {
        float v = 0.5f * proto[tid];
        sPc[tid] = cosf(v);
        sPs[tid] = sinf(v);
    }
    __syncthreads();

    const int warp_global = blockIdx.x * 4 + (tid >> 5);
    const int lane  = tid & 31;
    const int group = warp_global >> 4;   // 0..63
    const int chunk = warp_global & 15;   // 0..15

    // patches [pstart, pstart+pcnt): first 4 chunks get 13, rest 12 (total 196)
    const int pstart = chunk * 12 + min(chunk, 4);
    const int pcnt   = 12 + (chunk < 4 ? 1 : 0);

    const int img0 = group * 128 + lane;

    float acc[RIMG][NCLS];
    #pragma unroll
    for (int r = 0; r < RIMG; ++r)
        #pragma unroll
        for (int c = 0; c < NCLS; ++c) acc[r][c] = 0.0f;

    const float* xb0 = x + (size_t)(img0     ) * 784;
    const float* xb1 = x + (size_t)(img0 + 32) * 784;
    const float* xb2 = x + (size_t)(img0 + 64) * 784;
    const float* xb3 = x + (size_t)(img0 + 96) * 784;

    for (int pi = pstart; pi < pstart + pcnt; ++pi) {
        const int pr  = pi / 14;
        const int pc  = pi - pr * 14;
        const int off = pr * 56 + pc * 2;   // even -> 8B aligned float2 loads

        float cx[RIMG][4], sx[RIMG][4];
        const float* xb[RIMG] = { xb0, xb1, xb2, xb3 };
        #pragma unroll
        for (int r = 0; r < RIMG; ++r) {
            float2 a  = *reinterpret_cast<const float2*>(xb[r] + off);
            float2 b2 = *reinterpret_cast<const float2*>(xb[r] + off + 28);
            __sincosf(0.5f * a.x,  &sx[r][0], &cx[r][0]);
            __sincosf(0.5f * a.y,  &sx[r][1], &cx[r][1]);
            __sincosf(0.5f * b2.x, &sx[r][2], &cx[r][2]);
            __sincosf(0.5f * b2.y, &sx[r][3], &cx[r][3]);
        }

        #pragma unroll
        for (int p = 0; p < NPROTO; ++p) {
            const float cy0 = sPc[p*4+0], cy1 = sPc[p*4+1];
            const float cy2 = sPc[p*4+2], cy3 = sPc[p*4+3];
            const float sy0 = sPs[p*4+0], sy1 = sPs[p*4+1];
            const float sy2 = sPs[p*4+2], sy3 = sPs[p*4+3];

            float k[RIMG];
            #pragma unroll
            for (int r = 0; r < RIMG; ++r) {
                // cos((x-y)/2) = cos(x/2)cos(y/2) + sin(x/2)sin(y/2)
                float t0 = fmaf(cx[r][0], cy0, sx[r][0] * sy0);
                float t1 = fmaf(cx[r][1], cy1, sx[r][1] * sy1);
                float t2 = fmaf(cx[r][2], cy2, sx[r][2] * sy2);
                float t3 = fmaf(cx[r][3], cy3, sx[r][3] * sy3);
                k[r] = fabsf((t0 * t1) * (t2 * t3));
            }

            const float* wp = sW + p * NPATCH + pi;  // warp-uniform address
            #pragma unroll
            for (int c = 0; c < NCLS; ++c) {
                const float w = wp[c * NFEAT];       // broadcast LDS
                #pragma unroll
                for (int r = 0; r < RIMG; ++r)
                    acc[r][c] = fmaf(k[r], w, acc[r][c]);
            }
        }
    }

    float* outp = g_scratch + (size_t)(chunk * NGROUP + group) * (NCLS * RIMG * 32);
    #pragma unroll
    for (int c = 0; c < NCLS; ++c)
        #pragma unroll
        for (int r = 0; r < RIMG; ++r)
            outp[(c * RIMG + r) * 32 + lane] = acc[r][c];
}

// ---------------------------------------------------------------------------
// Stage 2: reduce 16 partial chunks, add bias, log_softmax over 10 classes.
// ---------------------------------------------------------------------------
__global__ void __launch_bounds__(128)
quanv_stage2(const float* __restrict__ bias, float* __restrict__ out)
{
    const int img = blockIdx.x * blockDim.x + threadIdx.x;
    if (img >= BIMG) return;
    const int lane  = img & 31;
    const int r     = (img >> 5) & 3;
    const int group = img >> 7;

    float logit[NCLS];
    #pragma unroll
    for (int c = 0; c < NCLS; ++c) logit[c] = bias[c];

    #pragma unroll
    for (int chunk = 0; chunk < NCHUNK; ++chunk) {
        const float* sp = g_scratch + (size_t)(chunk * NGROUP + group) * (NCLS * RIMG * 32);
        #pragma unroll
        for (int c = 0; c < NCLS; ++c)
            logit[c] += sp[(c * RIMG + r) * 32 + lane];
    }

    float m = logit[0];
    #pragma unroll
    for (int c = 1; c < NCLS; ++c) m = fmaxf(m, logit[c]);
    float s = 0.0f;
    #pragma unroll
    for (int c = 0; c < NCLS; ++c) s += expf(logit[c] - m);
    const float lse = m + logf(s);   // full log-sum-exp

    #pragma unroll
    for (int c = 0; c < NCLS; ++c) out[img * NCLS + c] = logit[c] - lse;  // FIXED: was logit - m - lse
}

// ---------------------------------------------------------------------------
extern "C" void kernel_launch(void* const* d_in, const int* in_sizes, int n_in,
                              void* d_out, int out_size)
{
    const float* x     = (const float*)d_in[0];  // (8192, 784)
    const float* proto = (const float*)d_in[1];  // (10, 4)
    const float* W     = (const float*)d_in[2];  // (10, 1960)
    const float* bias  = (const float*)d_in[3];  // (10,)
    float* out = (float*)d_out;                  // (8192, 10)

    const int smem_bytes = (NCLS * NFEAT + 80) * (int)sizeof(float); // 78,720 B
    cudaFuncSetAttribute(quanv_stage1,
                         cudaFuncAttributeMaxDynamicSharedMemorySize, smem_bytes);

    quanv_stage1<<<(NGROUP * NCHUNK) / 4, 128, smem_bytes>>>(x, proto, W);
    quanv_stage2<<<BIMG / 128, 128>>>(bias, out);
}

// round 3
// speedup vs baseline: 1.2541x; 1.2541x over previous
#include <cuda_runtime.h>
#include <math.h>

#define NPROTO  10
#define NCLS    10
#define NPATCH  196
#define BIMG    8192
#define NFEAT   1960
#define NCHUNK  16
#define NGROUP  64          // 8192 / 128 images per warp

typedef unsigned long long u64;

// scratch: [chunk][group][c*2+rp][lane] of packed float2 (two images per entry)
__device__ u64 g_scratch[NCHUNK * NGROUP * (NCLS * 2) * 32];   // 5.24 MB

// ---- packed f32x2 helpers (sm_103a FFMA2 path) ------------------------------
__device__ __forceinline__ u64 pk2(float lo, float hi) {
    u64 r; asm("mov.b64 %0, {%1,%2};" : "=l"(r) : "f"(lo), "f"(hi)); return r;
}
__device__ __forceinline__ u64 fma2(u64 a, u64 b, u64 c) {
    u64 d; asm("fma.rn.f32x2 %0, %1, %2, %3;" : "=l"(d) : "l"(a), "l"(b), "l"(c)); return d;
}
__device__ __forceinline__ u64 mul2(u64 a, u64 b) {
    u64 d; asm("mul.rn.f32x2 %0, %1, %2;" : "=l"(d) : "l"(a), "l"(b)); return d;
}

// ---------------------------------------------------------------------------
// Stage 1: fused quantum-kernel features + partial class GEMM, f32x2-packed.
// Grid 256 x 128. CTA = one patch chunk, 4 warps = 4 image groups.
// Each lane owns 4 images as two f32x2 pairs: P0=(img0,img0+32), P1=(+64,+96).
// All smem operand arrays are stored as duplicated (v,v) pairs so a single
// broadcast LDS.64/128 produces a packed splat operand for FFMA2.
// ---------------------------------------------------------------------------
__global__ void __launch_bounds__(128)
quanv_stage1(const float* __restrict__ x,
             const float* __restrict__ proto,
             const float* __restrict__ W)
{
    __shared__ __align__(16) float2 sPc2[NPROTO * 4];   // (cos(y/2), cos(y/2))
    __shared__ __align__(16) float2 sPs2[NPROTO * 4];   // (sin(y/2), sin(y/2))
    __shared__ __align__(16) float2 sW2[13 * 100];      // [li][p][c] -> (w,w)

    const int tid    = threadIdx.x;
    const int chunk  = blockIdx.x >> 4;                 // 0..15
    const int pstart = chunk * 12 + min(chunk, 4);
    const int pcnt   = 12 + (chunk < 4 ? 1 : 0);

    for (int i = tid; i < pcnt * 100; i += 128) {
        int li  = i / 100, rem = i - li * 100;
        int p   = rem / 10, c = rem - p * 10;
        float w = W[c * NFEAT + p * NPATCH + pstart + li];
        sW2[i]  = make_float2(w, w);
    }
    if (tid < NPROTO * 4) {
        float v = 0.5f * proto[tid];
        float s, cth; __sincosf(v, &s, &cth);
        sPc2[tid] = make_float2(cth, cth);
        sPs2[tid] = make_float2(s, s);
    }
    __syncthreads();

    const int wid   = tid >> 5, lane = tid & 31;
    const int group = (blockIdx.x & 15) * 4 + wid;      // 0..63
    const int img0  = group * 128 + lane;

    const float* xb0 = x + (size_t)(img0     ) * 784;
    const float* xb1 = x + (size_t)(img0 + 32) * 784;
    const float* xb2 = x + (size_t)(img0 + 64) * 784;
    const float* xb3 = x + (size_t)(img0 + 96) * 784;

    u64 acc[2][NCLS];
    #pragma unroll
    for (int rp = 0; rp < 2; ++rp)
        #pragma unroll
        for (int c = 0; c < NCLS; ++c) acc[rp][c] = 0ULL;   // bits of (0.f,0.f)

    for (int li = 0; li < pcnt; ++li) {
        const int pi  = pstart + li;
        const int pr  = pi / 14;
        const int pc  = pi - pr * 14;
        const int off = pr * 56 + pc * 2;

        // sincos of the 4 patch pixels for 4 images, then pack over image pairs
        float cs[4][4], sn[4][4];
        const float* xb[4] = { xb0, xb1, xb2, xb3 };
        #pragma unroll
        for (int r = 0; r < 4; ++r) {
            float2 a  = *reinterpret_cast<const float2*>(xb[r] + off);
            float2 b2 = *reinterpret_cast<const float2*>(xb[r] + off + 28);
            __sincosf(0.5f * a.x,  &sn[r][0], &cs[r][0]);
            __sincosf(0.5f * a.y,  &sn[r][1], &cs[r][1]);
            __sincosf(0.5f * b2.x, &sn[r][2], &cs[r][2]);
            __sincosf(0.5f * b2.y, &sn[r][3], &cs[r][3]);
        }
        u64 cxp[2][4], sxp[2][4];
        #pragma unroll
        for (int j = 0; j < 4; ++j) {
            cxp[0][j] = pk2(cs[0][j], cs[1][j]);
            cxp[1][j] = pk2(cs[2][j], cs[3][j]);
            sxp[0][j] = pk2(sn[0][j], sn[1][j]);
            sxp[1][j] = pk2(sn[2][j], sn[3][j]);
        }

        const float2* wrow = &sW2[li * 100];

        #pragma unroll
        for (int p = 0; p < NPROTO; ++p) {
            // packed proto splats: 4x LDS.128 broadcast
            ulonglong2 cyA = *reinterpret_cast<const ulonglong2*>(&sPc2[p * 4]);
            ulonglong2 cyB = *reinterpret_cast<const ulonglong2*>(&sPc2[p * 4 + 2]);
            ulonglong2 syA = *reinterpret_cast<const ulonglong2*>(&sPs2[p * 4]);
            ulonglong2 syB = *reinterpret_cast<const ulonglong2*>(&sPs2[p * 4 + 2]);

            u64 kq[2];
            #pragma unroll
            for (int rp = 0; rp < 2; ++rp) {
                // cos((x-y)/2) = cos(x/2)cos(y/2) + sin(x/2)sin(y/2), 2 images/op
                u64 t0 = fma2(cxp[rp][0], cyA.x, mul2(sxp[rp][0], syA.x));
                u64 t1 = fma2(cxp[rp][1], cyA.y, mul2(sxp[rp][1], syA.y));
                u64 t2 = fma2(cxp[rp][2], cyB.x, mul2(sxp[rp][2], syB.x));
                u64 t3 = fma2(cxp[rp][3], cyB.y, mul2(sxp[rp][3], syB.y));
                kq[rp] = mul2(mul2(t0, t1), mul2(t2, t3)) & 0x7FFFFFFF7FFFFFFFULL;
            }

            const ulonglong2* wp = reinterpret_cast<const ulonglong2*>(wrow + p * 10);
            #pragma unroll
            for (int cc = 0; cc < 5; ++cc) {            // 2 classes per LDS.128
                ulonglong2 wv = wp[cc];
                acc[0][cc*2  ] = fma2(kq[0], wv.x, acc[0][cc*2  ]);
                acc[1][cc*2  ] = fma2(kq[1], wv.x, acc[1][cc*2  ]);
                acc[0][cc*2+1] = fma2(kq[0], wv.y, acc[0][cc*2+1]);
                acc[1][cc*2+1] = fma2(kq[1], wv.y, acc[1][cc*2+1]);
            }
        }
    }

    // coalesced packed store: 20 STG.64 per lane
    u64* outp = g_scratch + (size_t)(chunk * NGROUP + group) * (NCLS * 2) * 32;
    #pragma unroll
    for (int c = 0; c < NCLS; ++c) {
        outp[(c * 2 + 0) * 32 + lane] = acc[0][c];
        outp[(c * 2 + 1) * 32 + lane] = acc[1][c];
    }
}

// ---------------------------------------------------------------------------
// Stage 2: 64 CTAs x 256. Warp w of a CTA: rp=w&1, chunk-quarter q=w>>1.
// Each thread sums 4 chunks x 10 classes of one packed float2 (2 images):
// 40 independent coalesced LDG.64 -> high MLP. Cross-warp reduce in smem,
// then 128 threads finish bias + log_softmax (one image each).
// ---------------------------------------------------------------------------
__global__ void __launch_bounds__(256)
quanv_stage2(const float* __restrict__ bias, float* __restrict__ out)
{
    __shared__ float2 spart[4][2][32][NCLS];   // [q][rp][lane][c], 20.5 KB

    const int g    = blockIdx.x;               // image group 0..63
    const int tid  = threadIdx.x;
    const int w    = tid >> 5, lane = tid & 31;
    const int q    = w >> 1,  rp   = w & 1;

    float2 plog[NCLS];
    #pragma unroll
    for (int c = 0; c < NCLS; ++c) plog[c] = make_float2(0.f, 0.f);

    #pragma unroll
    for (int k = 0; k < 4; ++k) {
        const int chunk = q * 4 + k;
        const u64* sp = g_scratch + (size_t)(chunk * NGROUP + g) * (NCLS * 2) * 32;
        #pragma unroll
        for (int c = 0; c < NCLS; ++c) {
            u64 v = sp[(c * 2 + rp) * 32 + lane];
            float2 f = *reinterpret_cast<float2*>(&v);
            plog[c].x += f.x;
            plog[c].y += f.y;
        }
    }
    #pragma unroll
    for (int c = 0; c < NCLS; ++c) spart[q][rp][lane][c] = plog[c];
    __syncthreads();

    if (tid < 128) {
        const int r   = tid >> 5, l2 = tid & 31;
        const int rp2 = r >> 1,   hi = r & 1;

        float logit[NCLS];
        #pragma unroll
        for (int c = 0; c < NCLS; ++c) {
            float s = bias[c];
            #pragma unroll
            for (int qq = 0; qq < 4; ++qq) {
                float2 f = spart[qq][rp2][l2][c];
                s += hi ? f.y : f.x;
            }
            logit[c] = s;
        }

        float m = logit[0];
        #pragma unroll
        for (int c = 1; c < NCLS; ++c) m = fmaxf(m, logit[c]);
        float ssum = 0.f;
        #pragma unroll
        for (int c = 0; c < NCLS; ++c) ssum += expf(logit[c] - m);
        const float lse = m + logf(ssum);

        const int img = g * 128 + tid;          // tid = r*32 + l2 matches stage1 map
        #pragma unroll
        for (int c = 0; c < NCLS; ++c) out[img * NCLS + c] = logit[c] - lse;
    }
}

// ---------------------------------------------------------------------------
extern "C" void kernel_launch(void* const* d_in, const int* in_sizes, int n_in,
                              void* d_out, int out_size)
{
    const float* x     = (const float*)d_in[0];  // (8192, 784)
    const float* proto = (const float*)d_in[1];  // (10, 4)
    const float* W     = (const float*)d_in[2];  // (10, 1960)
    const float* bias  = (const float*)d_in[3];  // (10,)
    float* out = (float*)d_out;                  // (8192, 10)

    quanv_stage1<<<NCHUNK * (NGROUP / 4), 128>>>(x, proto, W);  // 256 CTAs
    quanv_stage2<<<NGROUP, 256>>>(bias, out);                   // 64 CTAs
}